// round 17
// baseline (speedup 1.0000x reference)
#include <cuda_runtime.h>

// DropBlock: x [64,256,64,64] f32, u [58,58] f32. BLOCK_SIZE=7, DROP_PROB=0.1
// Mask is ~99.4% zeros (P(keep)=0.9^49~0.6%).
//   1. cudaMemsetAsync(out, 0) — driver fill kernel = best write stream.
//   2. fixup kernel: each CTA recomputes the mask (ballot bitboards, ~1us,
//      parallel), compacts kept columns, and each warp patches one (n,c)
//      plane: out[q] = x[q] * m[q] for the ~23 kept float4 columns.

#define H 64
#define W 64
#define HW 4096
#define US 58           // H - BS + 1
#define BS 7
#define DROP_PROB 0.1f
#define THREADS 256
#define PLANES_PER_CTA 8   // one plane per warp

typedef unsigned long long u64;

__global__ __launch_bounds__(THREADS)
void fixup_kernel(const float* __restrict__ u,
                  const float4* __restrict__ x4,
                  float4* __restrict__ out4,
                  int planes) {
    __shared__ u64 s_hdil[US];
    __shared__ u64 s_vdil[H];
    __shared__ int s_sum;
    __shared__ int s_cnt;
    __shared__ short s_q[1024];                    // kept float4 column ids
    __shared__ __align__(16) float4 s_m[1024];     // their multipliers

    int tid  = threadIdx.x;
    int lane = tid & 31;
    int warp = tid >> 5;
    if (tid == 0) { s_sum = 0; s_cnt = 0; }

    // ---- mask via ballots: warp w -> rows w, w+8, ..., front-batched loads ----
    float va[8], vb[8];
    #pragma unroll
    for (int k = 0; k < 8; k++) {
        int row = warp + k * 8;
        if (row < US) {
            const float* r = u + row * US;
            va[k] = __ldg(&r[lane]);
            vb[k] = (lane + 32 < US) ? __ldg(&r[lane + 32]) : 1.0f;
        } else { va[k] = 1.0f; vb[k] = 1.0f; }
    }
    #pragma unroll
    for (int k = 0; k < 8; k++) {
        int row = warp + k * 8;
        unsigned m0 = __ballot_sync(0xFFFFFFFFu, va[k] < DROP_PROB);
        unsigned m1 = __ballot_sync(0xFFFFFFFFu, vb[k] < DROP_PROB);
        if (row < US && lane == 0) {
            u64 b = (u64)m0 | ((u64)m1 << 32);
            u64 h = b;
            #pragma unroll
            for (int s = 1; s < BS; s++) h |= b << s;   // horizontal dilation
            s_hdil[row] = h;
        }
    }
    __syncthreads();

    if (tid < H) {
        int i0 = tid - (BS - 1); if (i0 < 0) i0 = 0;
        int i1 = tid;            if (i1 > US - 1) i1 = US - 1;
        u64 v = 0ULL;
        for (int i = i0; i <= i1; i++) v |= s_hdil[i];
        s_vdil[tid] = v;
        int keep = W - __popcll(v);
        #pragma unroll
        for (int off = 16; off > 0; off >>= 1)
            keep += __shfl_down_sync(0xFFFFFFFFu, keep, off);
        if (lane == 0) atomicAdd(&s_sum, keep);
    }
    __syncthreads();

    float scale = (float)HW / (float)s_sum;

    // compact kept float4 columns (1024 columns over 256 threads)
    #pragma unroll
    for (int k = 0; k < 4; k++) {
        int q = tid + k * 256;
        int y = q >> 4;
        int x = (q & 15) * 4;
        u64 v = s_vdil[y];
        unsigned dropped4 = (unsigned)((v >> x) & 0xFULL);
        if (dropped4 != 0xFu) {
            float4 f;
            f.x = (dropped4 & 1u) ? 0.0f : scale;
            f.y = (dropped4 & 2u) ? 0.0f : scale;
            f.z = (dropped4 & 4u) ? 0.0f : scale;
            f.w = (dropped4 & 8u) ? 0.0f : scale;
            int pos = atomicAdd(&s_cnt, 1);
            s_q[pos] = (short)q;
            s_m[pos] = f;
        }
    }
    __syncthreads();
    int cnt = s_cnt;

    // ---- patch kept columns: one warp per plane ----
    int plane = blockIdx.x * PLANES_PER_CTA + warp;
    if (plane >= planes) return;
    int base = plane << 10;                 // 1024 float4s per (n,c) plane

    for (int k = lane; k < cnt; k += 32) {
        int q = s_q[k];
        float4 m = s_m[k];
        float4 v = x4[base + q];
        v.x *= m.x; v.y *= m.y; v.z *= m.z; v.w *= m.w;
        out4[base + q] = v;
    }
}

extern "C" void kernel_launch(void* const* d_in, const int* in_sizes, int n_in,
                              void* d_out, int out_size) {
    const float* x = (const float*)d_in[0];
    const float* u = (const float*)d_in[1];
    float* out = (float*)d_out;

    // 1. zero the whole output via the driver's fill path (graph memset node)
    cudaMemsetAsync(d_out, 0, (size_t)out_size * sizeof(float), 0);

    // 2. patch the ~0.6% kept columns
    int n4 = out_size / 4;        // 16,777,216 float4s
    int planes = n4 >> 10;        // 16384 (n,c) planes
    int blocks = (planes + PLANES_PER_CTA - 1) / PLANES_PER_CTA;
    fixup_kernel<<<blocks, THREADS>>>(
        u, (const float4*)x, (float4*)out, planes);
}